// round 3
// baseline (speedup 1.0000x reference)
#include <cuda_runtime.h>

constexpr int N   = 100000;
constexpr int E   = 3200000;
constexpr int FIN = 512;
constexpr int TILES = (N + 255) / 256;      // 391
constexpr int SCAN_BLOCKS = 98;             // ceil(N/1024)
constexpr int SMEM_FLOATS = 8192 + 16 * 257;  // W1 + x-tile
constexpr int SMEM_BYTES  = SMEM_FLOATS * 4;  // 49216

__device__ int    g_cnt[N];
__device__ int    g_agg[SCAN_BLOCKS];
__device__ int    g_rowptr[N + 1];
__device__ int    g_cur[N];
__device__ int    g_csrc[E];
__device__ float  g_dinv[N];
__device__ float4 g_h1[N * 4];
__device__ float4 g_h2[N * 4];
__device__ unsigned g_bar;

__global__ void k_reset() { g_bar = 0u; }

__device__ __forceinline__ void ffma2(unsigned long long& d,
                                      unsigned long long a,
                                      unsigned long long b) {
    asm("fma.rn.f32x2 %0, %1, %2, %0;" : "+l"(d) : "l"(a), "l"(b));
}
__device__ __forceinline__ unsigned long long bcast2(float v) {
    unsigned long long r;
    asm("mov.b64 %0, {%1, %1};" : "=l"(r) : "f"(v));
    return r;
}
__device__ __forceinline__ float2 unpack2(unsigned long long v) {
    float2 r;
    asm("mov.b64 {%0, %1}, %2;" : "=f"(r.x), "=f"(r.y) : "l"(v));
    return r;
}

__device__ __forceinline__ void gsync(unsigned target) {
    __syncthreads();
    if (threadIdx.x == 0) {
        __threadfence();
        atomicAdd(&g_bar, 1u);
        while (*(volatile unsigned*)&g_bar < target) __nanosleep(64);
    }
    __syncthreads();
}

__global__ void __launch_bounds__(256, 4) k_mega(
    const float* __restrict__ x,  const float* __restrict__ W1,
    const float* __restrict__ b1, const float* __restrict__ W2,
    const float* __restrict__ b2, const int*   __restrict__ ei,
    float* __restrict__ out)
{
    extern __shared__ float sm[];        // [0,8192) = W1, [8192,..) = x tile / W2
    __shared__ int sh[256];

    const int t   = threadIdx.x;
    const int bid = blockIdx.x;
    const int G   = gridDim.x;
    const unsigned tid_g = (unsigned)bid * 256u + t;
    const unsigned nthr  = (unsigned)G * 256u;

    // ---- phase 0: zero degree counters ----
    for (unsigned i = tid_g; i < (unsigned)N; i += nthr) g_cnt[i] = 0;
    gsync(1u * G);

    // ---- phase 1: GEMM1 (blocks < GB)  ||  histogram (rest) ----
    {
        int GB = G - 32; if (GB > TILES) GB = TILES;
        if (bid < GB) {
            const float4* w4 = (const float4*)W1;
            float4* s4 = (float4*)sm;
            for (int i = t; i < 2048; i += 256) s4[i] = __ldg(&w4[i]);
            float* xs = sm + 8192;
            for (int tile = bid; tile < TILES; tile += GB) {
                const int row0 = tile * 256;
                const int row  = row0 + t;
                unsigned long long acc[8];
#pragma unroll
                for (int j = 0; j < 8; ++j) acc[j] = 0ull;
                for (int kt = 0; kt < FIN / 16; ++kt) {
                    __syncthreads();
#pragma unroll
                    for (int i = 0; i < 4; ++i) {
                        int fid = i * 256 + t;
                        int r = fid >> 2, j = fid & 3;
                        int gr = row0 + r; if (gr >= N) gr = N - 1;
                        float4 xv = __ldg((const float4*)(x + (size_t)gr * FIN + kt * 16 + j * 4));
                        xs[(j * 4 + 0) * 257 + r] = xv.x;
                        xs[(j * 4 + 1) * 257 + r] = xv.y;
                        xs[(j * 4 + 2) * 257 + r] = xv.z;
                        xs[(j * 4 + 3) * 257 + r] = xv.w;
                    }
                    __syncthreads();
#pragma unroll
                    for (int kk = 0; kk < 16; ++kk) {
                        unsigned long long xx = bcast2(xs[kk * 257 + t]);
                        const ulonglong2* wr = (const ulonglong2*)(sm + (kt * 16 + kk) * 16);
                        ulonglong2 w0 = wr[0], w1 = wr[1], w2 = wr[2], w3 = wr[3];
                        ffma2(acc[0], xx, w0.x); ffma2(acc[1], xx, w0.y);
                        ffma2(acc[2], xx, w1.x); ffma2(acc[3], xx, w1.y);
                        ffma2(acc[4], xx, w2.x); ffma2(acc[5], xx, w2.y);
                        ffma2(acc[6], xx, w3.x); ffma2(acc[7], xx, w3.y);
                    }
                }
                if (row < N) {
                    float4* dst = &g_h1[(size_t)row * 4];
#pragma unroll
                    for (int q = 0; q < 4; ++q) {
                        float2 lo = unpack2(acc[2 * q]);
                        float2 hi = unpack2(acc[2 * q + 1]);
                        dst[q] = make_float4(lo.x, lo.y, hi.x, hi.y);
                    }
                }
            }
        } else {
            const int HB = G - GB;
            const int4* d4 = (const int4*)(ei + E);
            for (int i = (bid - GB) * 256 + t; i < E / 4; i += HB * 256) {
                int4 d = __ldg(&d4[i]);
                atomicAdd(&g_cnt[d.x], 1);
                atomicAdd(&g_cnt[d.y], 1);
                atomicAdd(&g_cnt[d.z], 1);
                atomicAdd(&g_cnt[d.w], 1);
            }
        }
    }
    gsync(2u * G);

    // ---- phase 2: block-local inclusive scan of degrees ----
    if (bid < SCAN_BLOCKS) {
        const int i0 = bid * 1024 + t * 4;
        int v0 = (i0 + 0 < N) ? __ldcg(&g_cnt[i0 + 0]) : 0;
        int v1 = (i0 + 1 < N) ? __ldcg(&g_cnt[i0 + 1]) : 0;
        int v2 = (i0 + 2 < N) ? __ldcg(&g_cnt[i0 + 2]) : 0;
        int v3 = (i0 + 3 < N) ? __ldcg(&g_cnt[i0 + 3]) : 0;
        int tot = v0 + v1 + v2 + v3;
        sh[t] = tot;
        __syncthreads();
#pragma unroll
        for (int o = 1; o < 256; o <<= 1) {
            int a = (t >= o) ? sh[t - o] : 0;
            __syncthreads();
            sh[t] += a;
            __syncthreads();
        }
        int e0 = sh[t] - tot;
        if (t == 255) g_agg[bid] = sh[255];
        if (i0 + 0 < N) g_rowptr[i0 + 0] = e0 + v0;
        if (i0 + 1 < N) g_rowptr[i0 + 1] = e0 + v0 + v1;
        if (i0 + 2 < N) g_rowptr[i0 + 2] = e0 + v0 + v1 + v2;
        if (i0 + 3 < N) g_rowptr[i0 + 3] = e0 + v0 + v1 + v2 + v3;
    }
    gsync(3u * G);

    // ---- phase 3: add block bases; emit rowptr/cur/dinv ----
    if (bid < SCAN_BLOCKS) {
        sh[t] = (t < bid) ? __ldcg(&g_agg[t]) : 0;
        __syncthreads();
#pragma unroll
        for (int o = 128; o > 0; o >>= 1) {
            if (t < o) sh[t] += sh[t + o];
            __syncthreads();
        }
        const int base = sh[0];
        const int i0 = bid * 1024 + t * 4;
#pragma unroll
        for (int u = 0; u < 4; ++u) {
            int i = i0 + u;
            if (i < N) {
                int v = __ldcg(&g_cnt[i]);
                int excl = base + g_rowptr[i] - v;
                g_rowptr[i] = excl;
                g_cur[i]    = excl;
                g_dinv[i]   = rsqrtf((float)(v + 1));
            }
        }
    }
    if (bid == 0 && t == 0) g_rowptr[N] = E;
    gsync(4u * G);

    // ---- phase 4: scatter CSR + scale h1 by dinv[row] ----
    {
        const int4* s4 = (const int4*)ei;
        const int4* d4 = (const int4*)(ei + E);
        for (unsigned i = tid_g; i < (unsigned)(E / 4); i += nthr) {
            int4 s = __ldg(&s4[i]);
            int4 d = __ldg(&d4[i]);
            g_csrc[atomicAdd(&g_cur[d.x], 1)] = s.x;
            g_csrc[atomicAdd(&g_cur[d.y], 1)] = s.y;
            g_csrc[atomicAdd(&g_cur[d.z], 1)] = s.z;
            g_csrc[atomicAdd(&g_cur[d.w], 1)] = s.w;
        }
        for (unsigned i = tid_g; i < (unsigned)(N * 4); i += nthr) {
            float dv = g_dinv[i >> 2];
            float4 v = g_h1[i];
            g_h1[i] = make_float4(v.x * dv, v.y * dv, v.z * dv, v.w * dv);
        }
    }
    gsync(5u * G);

    // ---- phase 5: agg1 + bias + relu + @W2 (one warp per node) ----
    {
        float4* w2s = (float4*)(sm + 8192);
        if (t < 64) w2s[t] = __ldg(&((const float4*)W2)[t]);
        __syncthreads();

        const int lane = t & 31, slot = lane >> 2, q = lane & 3;
        const int warps = (G * 256) >> 5;
        const float4 b1q = __ldg(&((const float4*)b1)[q]);

        for (int node = (int)(tid_g >> 5); node < N; node += warps) {
            const int start = g_rowptr[node], end = g_rowptr[node + 1];
            float4 acc = make_float4(0.f, 0.f, 0.f, 0.f);
            for (int base = start; base < end; base += 32) {
                int e = base + lane;
                int s = (e < end) ? g_csrc[e] : 0;
#pragma unroll
                for (int j = 0; j < 32; j += 8) {
                    int jj = j + slot;
                    int sj = __shfl_sync(0xffffffffu, s, jj);
                    if (base + jj < end) {
                        float4 hv = g_h1[(size_t)sj * 4 + q];
                        acc.x += hv.x; acc.y += hv.y; acc.z += hv.z; acc.w += hv.w;
                    }
                }
            }
#pragma unroll
            for (int o = 4; o < 32; o <<= 1) {
                acc.x += __shfl_xor_sync(0xffffffffu, acc.x, o);
                acc.y += __shfl_xor_sync(0xffffffffu, acc.y, o);
                acc.z += __shfl_xor_sync(0xffffffffu, acc.z, o);
                acc.w += __shfl_xor_sync(0xffffffffu, acc.w, o);
            }
            float dv = g_dinv[node];
            float4 sv = g_h1[(size_t)node * 4 + q];
            float4 r;
            r.x = fmaxf((acc.x + sv.x) * dv + b1q.x, 0.f);
            r.y = fmaxf((acc.y + sv.y) * dv + b1q.y, 0.f);
            r.z = fmaxf((acc.z + sv.z) * dv + b1q.z, 0.f);
            r.w = fmaxf((acc.w + sv.w) * dv + b1q.w, 0.f);

            float4 h2 = make_float4(0.f, 0.f, 0.f, 0.f);
#pragma unroll
            for (int qq = 0; qq < 4; ++qq) {
                float rx = __shfl_sync(0xffffffffu, r.x, qq);
                float ry = __shfl_sync(0xffffffffu, r.y, qq);
                float rz = __shfl_sync(0xffffffffu, r.z, qq);
                float rw = __shfl_sync(0xffffffffu, r.w, qq);
                float4 w0 = w2s[(qq * 4 + 0) * 4 + q];
                float4 w1 = w2s[(qq * 4 + 1) * 4 + q];
                float4 w2 = w2s[(qq * 4 + 2) * 4 + q];
                float4 w3 = w2s[(qq * 4 + 3) * 4 + q];
                h2.x = fmaf(rx, w0.x, fmaf(ry, w1.x, fmaf(rz, w2.x, fmaf(rw, w3.x, h2.x))));
                h2.y = fmaf(rx, w0.y, fmaf(ry, w1.y, fmaf(rz, w2.y, fmaf(rw, w3.y, h2.y))));
                h2.z = fmaf(rx, w0.z, fmaf(ry, w1.z, fmaf(rz, w2.z, fmaf(rw, w3.z, h2.z))));
                h2.w = fmaf(rx, w0.w, fmaf(ry, w1.w, fmaf(rz, w2.w, fmaf(rw, w3.w, h2.w))));
            }
            if (slot == 0)
                g_h2[(size_t)node * 4 + q] =
                    make_float4(h2.x * dv, h2.y * dv, h2.z * dv, h2.w * dv);
        }
    }
    gsync(6u * G);

    // ---- phase 6: agg2 + bias + log_softmax ----
    {
        const int lane = t & 31, slot = lane >> 2, q = lane & 3;
        const int warps = (G * 256) >> 5;
        const float4 b2q = __ldg(&((const float4*)b2)[q]);
        float4* out4 = (float4*)out;

        for (int node = (int)(tid_g >> 5); node < N; node += warps) {
            const int start = g_rowptr[node], end = g_rowptr[node + 1];
            float4 acc = make_float4(0.f, 0.f, 0.f, 0.f);
            for (int base = start; base < end; base += 32) {
                int e = base + lane;
                int s = (e < end) ? g_csrc[e] : 0;
#pragma unroll
                for (int j = 0; j < 32; j += 8) {
                    int jj = j + slot;
                    int sj = __shfl_sync(0xffffffffu, s, jj);
                    if (base + jj < end) {
                        float4 hv = g_h2[(size_t)sj * 4 + q];
                        acc.x += hv.x; acc.y += hv.y; acc.z += hv.z; acc.w += hv.w;
                    }
                }
            }
#pragma unroll
            for (int o = 4; o < 32; o <<= 1) {
                acc.x += __shfl_xor_sync(0xffffffffu, acc.x, o);
                acc.y += __shfl_xor_sync(0xffffffffu, acc.y, o);
                acc.z += __shfl_xor_sync(0xffffffffu, acc.z, o);
                acc.w += __shfl_xor_sync(0xffffffffu, acc.w, o);
            }
            float dv = g_dinv[node];
            float4 sv = g_h2[(size_t)node * 4 + q];
            float4 val;
            val.x = (acc.x + sv.x) * dv + b2q.x;
            val.y = (acc.y + sv.y) * dv + b2q.y;
            val.z = (acc.z + sv.z) * dv + b2q.z;
            val.w = (acc.w + sv.w) * dv + b2q.w;

            float m = fmaxf(fmaxf(val.x, val.y), fmaxf(val.z, val.w));
            m = fmaxf(m, __shfl_xor_sync(0xffffffffu, m, 1));
            m = fmaxf(m, __shfl_xor_sync(0xffffffffu, m, 2));
            float ssum = __expf(val.x - m) + __expf(val.y - m) +
                         __expf(val.z - m) + __expf(val.w - m);
            ssum += __shfl_xor_sync(0xffffffffu, ssum, 1);
            ssum += __shfl_xor_sync(0xffffffffu, ssum, 2);
            float lse = m + __logf(ssum);
            if (slot == 0)
                out4[(size_t)node * 4 + q] =
                    make_float4(val.x - lse, val.y - lse, val.z - lse, val.w - lse);
        }
    }
}

extern "C" void kernel_launch(void* const* d_in, const int* in_sizes, int n_in,
                              void* d_out, int out_size) {
    const float* x  = (const float*)d_in[0];
    const float* W1 = (const float*)d_in[1];
    const float* b1 = (const float*)d_in[2];
    const float* W2 = (const float*)d_in[3];
    const float* b2 = (const float*)d_in[4];
    const int*   ei = (const int*)d_in[5];
    float* out = (float*)d_out;

    int dev = 0;
    cudaGetDevice(&dev);
    int nsm = 0;
    cudaDeviceGetAttribute(&nsm, cudaDevAttrMultiProcessorCount, dev);
    cudaFuncSetAttribute((const void*)k_mega,
                         cudaFuncAttributeMaxDynamicSharedMemorySize, SMEM_BYTES);
    int occ = 0;
    cudaOccupancyMaxActiveBlocksPerMultiprocessor(&occ, k_mega, 256, SMEM_BYTES);
    if (occ < 1) occ = 1;
    int G = occ * nsm;

    k_reset<<<1, 1>>>();
    k_mega<<<G, 256, SMEM_BYTES>>>(x, W1, b1, W2, b2, ei, out);
}

// round 4
// speedup vs baseline: 1.1779x; 1.1779x over previous
#include <cuda_runtime.h>

constexpr int N   = 100000;
constexpr int E   = 3200000;
constexpr int FIN = 512;
constexpr int TILES = (N + 255) / 256;        // 391
constexpr int SCAN_BLOCKS = 98;               // ceil(N/1024)
constexpr int GB = TILES;                     // gemm blocks in k1
constexpr int HB = 128;                       // hist blocks in k1
constexpr int GRID1 = GB + HB;                // 519
constexpr int SMEM_FLOATS = 8192 + 16 * 257;  // W1 + x-tile
constexpr int SMEM_BYTES  = SMEM_FLOATS * 4;  // 49216

// scratch (zero-initialized at module load; self-cleaned each run)
__device__ int    g_cnt[N];          // degree hist; zeroed by k_scan after use
__device__ int    g_aggA[SCAN_BLOCKS];
__device__ int    g_ready;           // reset by k1 each run
__device__ int    g_rowptr[N + 1];
__device__ int    g_cur[N];
__device__ int    g_csrc[E];
__device__ float  g_dinv[N];
__device__ float4 g_h1[N * 4];
__device__ float4 g_h2[N * 4];

__device__ __forceinline__ void ffma2(unsigned long long& d,
                                      unsigned long long a,
                                      unsigned long long b) {
    asm("fma.rn.f32x2 %0, %1, %2, %0;" : "+l"(d) : "l"(a), "l"(b));
}
__device__ __forceinline__ unsigned long long bcast2(float v) {
    unsigned long long r;
    asm("mov.b64 %0, {%1, %1};" : "=l"(r) : "f"(v));
    return r;
}
__device__ __forceinline__ float2 unpack2(unsigned long long v) {
    float2 r;
    asm("mov.b64 {%0, %1}, %2;" : "=f"(r.x), "=f"(r.y) : "l"(v));
    return r;
}

// ---------------- k1: GEMM1 (h1 = x@W1, unscaled) || degree histogram ----------------
__global__ void __launch_bounds__(256, 4) k1(
    const float* __restrict__ x, const float* __restrict__ W1,
    const int* __restrict__ ei)
{
    extern __shared__ float sm[];
    const int t = threadIdx.x, bid = blockIdx.x;

    if (bid < GB) {
        // ---- GEMM: one 256-row tile per block ----
        const float4* w4 = (const float4*)W1;
        float4* s4 = (float4*)sm;
        for (int i = t; i < 2048; i += 256) s4[i] = __ldg(&w4[i]);
        float* xs = sm + 8192;

        const int row0 = bid * 256;
        const int row  = row0 + t;
        unsigned long long acc[8];
#pragma unroll
        for (int j = 0; j < 8; ++j) acc[j] = 0ull;

        for (int kt = 0; kt < FIN / 16; ++kt) {
            __syncthreads();
#pragma unroll
            for (int i = 0; i < 4; ++i) {
                int fid = i * 256 + t;
                int r = fid >> 2, j = fid & 3;
                int gr = row0 + r; if (gr >= N) gr = N - 1;
                float4 xv = __ldg((const float4*)(x + (size_t)gr * FIN + kt * 16 + j * 4));
                xs[(j * 4 + 0) * 257 + r] = xv.x;
                xs[(j * 4 + 1) * 257 + r] = xv.y;
                xs[(j * 4 + 2) * 257 + r] = xv.z;
                xs[(j * 4 + 3) * 257 + r] = xv.w;
            }
            __syncthreads();
#pragma unroll
            for (int kk = 0; kk < 16; ++kk) {
                unsigned long long xx = bcast2(xs[kk * 257 + t]);
                const ulonglong2* wr = (const ulonglong2*)(sm + (kt * 16 + kk) * 16);
                ulonglong2 w0 = wr[0], w1 = wr[1], w2 = wr[2], w3 = wr[3];
                ffma2(acc[0], xx, w0.x); ffma2(acc[1], xx, w0.y);
                ffma2(acc[2], xx, w1.x); ffma2(acc[3], xx, w1.y);
                ffma2(acc[4], xx, w2.x); ffma2(acc[5], xx, w2.y);
                ffma2(acc[6], xx, w3.x); ffma2(acc[7], xx, w3.y);
            }
        }
        if (row < N) {
            float4* dst = &g_h1[(size_t)row * 4];
#pragma unroll
            for (int q = 0; q < 4; ++q) {
                float2 lo = unpack2(acc[2 * q]);
                float2 hi = unpack2(acc[2 * q + 1]);
                dst[q] = make_float4(lo.x, lo.y, hi.x, hi.y);
            }
        }
    } else {
        // ---- histogram of dst degrees (g_cnt was zeroed by previous run's k_scan,
        //      or by static zero-init on the very first run) ----
        if (bid == GB && t == 0) g_ready = 0;   // reset scan flag for this run
        const int4* d4 = (const int4*)(ei + E);
        for (int i = (bid - GB) * 256 + t; i < E / 4; i += HB * 256) {
            int4 d = __ldg(&d4[i]);
            atomicAdd(&g_cnt[d.x], 1);
            atomicAdd(&g_cnt[d.y], 1);
            atomicAdd(&g_cnt[d.z], 1);
            atomicAdd(&g_cnt[d.w], 1);
        }
    }
}

// ---------------- k_scan: single-pass exclusive scan -> rowptr/cur/dinv; zeroes g_cnt ----------------
__global__ void k_scan() {
    __shared__ int sh[256];
    __shared__ int s_base;
    const int b = blockIdx.x, t = threadIdx.x;
    const int i0 = b * 1024 + t * 4;

    int v0 = (i0 + 0 < N) ? __ldcg(&g_cnt[i0 + 0]) : 0;
    int v1 = (i0 + 1 < N) ? __ldcg(&g_cnt[i0 + 1]) : 0;
    int v2 = (i0 + 2 < N) ? __ldcg(&g_cnt[i0 + 2]) : 0;
    int v3 = (i0 + 3 < N) ? __ldcg(&g_cnt[i0 + 3]) : 0;
    int tot = v0 + v1 + v2 + v3;

    sh[t] = tot;
    if (t == 0) s_base = 0;
    __syncthreads();
#pragma unroll
    for (int o = 1; o < 256; o <<= 1) {
        int a = (t >= o) ? sh[t - o] : 0;
        __syncthreads();
        sh[t] += a;
        __syncthreads();
    }
    int incl = sh[t];

    // publish block aggregate, then wait for all blocks
    if (t == 255) {
        g_aggA[b] = incl;
        __threadfence();
        atomicAdd(&g_ready, 1);
    }
    if (t == 0) {
        while (*(volatile int*)&g_ready < SCAN_BLOCKS) __nanosleep(32);
    }
    __syncthreads();
    __threadfence();
    if (t < b) atomicAdd(&s_base, __ldcg(&g_aggA[t]));   // b <= 97
    __syncthreads();

    int e0 = s_base + incl - tot;   // exclusive prefix of element i0
    if (i0 + 0 < N) {
        g_rowptr[i0 + 0] = e0;
        g_cur[i0 + 0]    = e0;
        g_dinv[i0 + 0]   = rsqrtf((float)(v0 + 1));
        g_cnt[i0 + 0]    = 0;
    }
    if (i0 + 1 < N) {
        g_rowptr[i0 + 1] = e0 + v0;
        g_cur[i0 + 1]    = e0 + v0;
        g_dinv[i0 + 1]   = rsqrtf((float)(v1 + 1));
        g_cnt[i0 + 1]    = 0;
    }
    if (i0 + 2 < N) {
        g_rowptr[i0 + 2] = e0 + v0 + v1;
        g_cur[i0 + 2]    = e0 + v0 + v1;
        g_dinv[i0 + 2]   = rsqrtf((float)(v2 + 1));
        g_cnt[i0 + 2]    = 0;
    }
    if (i0 + 3 < N) {
        g_rowptr[i0 + 3] = e0 + v0 + v1 + v2;
        g_cur[i0 + 3]    = e0 + v0 + v1 + v2;
        g_dinv[i0 + 3]   = rsqrtf((float)(v3 + 1));
        g_cnt[i0 + 3]    = 0;
    }
    if (b == 0 && t == 0) g_rowptr[N] = E;
}

// ---------------- k_scatter_scale: CSR fill + h1 *= dinv[row] ----------------
__global__ void k_scatter_scale(const int* __restrict__ ei) {
    const unsigned tid = blockIdx.x * blockDim.x + threadIdx.x;
    const unsigned nthr = gridDim.x * blockDim.x;
    const int4* s4 = (const int4*)ei;
    const int4* d4 = (const int4*)(ei + E);
    for (unsigned i = tid; i < (unsigned)(E / 4); i += nthr) {
        int4 s = __ldg(&s4[i]);
        int4 d = __ldg(&d4[i]);
        g_csrc[atomicAdd(&g_cur[d.x], 1)] = s.x;
        g_csrc[atomicAdd(&g_cur[d.y], 1)] = s.y;
        g_csrc[atomicAdd(&g_cur[d.z], 1)] = s.z;
        g_csrc[atomicAdd(&g_cur[d.w], 1)] = s.w;
    }
    for (unsigned i = tid; i < (unsigned)(N * 4); i += nthr) {
        float dv = g_dinv[i >> 2];
        float4 v = g_h1[i];
        g_h1[i] = make_float4(v.x * dv, v.y * dv, v.z * dv, v.w * dv);
    }
}

// ---------------- agg1: sum_in(h1s) + self, *dinv, +b1, relu, @W2, *dinv ----------------
__global__ void k_agg1(const float* __restrict__ b1, const float* __restrict__ W2) {
    __shared__ float4 w2s[64];
    const int t = threadIdx.x;
    if (t < 64) w2s[t] = __ldg(&((const float4*)W2)[t]);
    __syncthreads();

    const int node = (int)((blockIdx.x * blockDim.x + t) >> 5);
    if (node >= N) return;
    const int lane = t & 31, slot = lane >> 2, q = lane & 3;
    const float4 b1q = __ldg(&((const float4*)b1)[q]);

    const int start = g_rowptr[node], end = g_rowptr[node + 1];
    float4 acc = make_float4(0.f, 0.f, 0.f, 0.f);
    for (int base = start; base < end; base += 32) {
        int e = base + lane;
        int s = (e < end) ? __ldg(&g_csrc[e]) : 0;
#pragma unroll
        for (int j = 0; j < 32; j += 8) {
            int jj = j + slot;
            int sj = __shfl_sync(0xffffffffu, s, jj);
            if (base + jj < end) {
                float4 hv = g_h1[(size_t)sj * 4 + q];
                acc.x += hv.x; acc.y += hv.y; acc.z += hv.z; acc.w += hv.w;
            }
        }
    }
#pragma unroll
    for (int o = 4; o < 32; o <<= 1) {
        acc.x += __shfl_xor_sync(0xffffffffu, acc.x, o);
        acc.y += __shfl_xor_sync(0xffffffffu, acc.y, o);
        acc.z += __shfl_xor_sync(0xffffffffu, acc.z, o);
        acc.w += __shfl_xor_sync(0xffffffffu, acc.w, o);
    }
    float dv = g_dinv[node];
    float4 sv = g_h1[(size_t)node * 4 + q];
    float4 r;
    r.x = fmaxf((acc.x + sv.x) * dv + b1q.x, 0.f);
    r.y = fmaxf((acc.y + sv.y) * dv + b1q.y, 0.f);
    r.z = fmaxf((acc.z + sv.z) * dv + b1q.z, 0.f);
    r.w = fmaxf((acc.w + sv.w) * dv + b1q.w, 0.f);

    float4 h2 = make_float4(0.f, 0.f, 0.f, 0.f);
#pragma unroll
    for (int qq = 0; qq < 4; ++qq) {
        float rx = __shfl_sync(0xffffffffu, r.x, qq);
        float ry = __shfl_sync(0xffffffffu, r.y, qq);
        float rz = __shfl_sync(0xffffffffu, r.z, qq);
        float rw = __shfl_sync(0xffffffffu, r.w, qq);
        float4 w0 = w2s[(qq * 4 + 0) * 4 + q];
        float4 w1 = w2s[(qq * 4 + 1) * 4 + q];
        float4 w2v = w2s[(qq * 4 + 2) * 4 + q];
        float4 w3 = w2s[(qq * 4 + 3) * 4 + q];
        h2.x = fmaf(rx, w0.x, fmaf(ry, w1.x, fmaf(rz, w2v.x, fmaf(rw, w3.x, h2.x))));
        h2.y = fmaf(rx, w0.y, fmaf(ry, w1.y, fmaf(rz, w2v.y, fmaf(rw, w3.y, h2.y))));
        h2.z = fmaf(rx, w0.z, fmaf(ry, w1.z, fmaf(rz, w2v.z, fmaf(rw, w3.z, h2.z))));
        h2.w = fmaf(rx, w0.w, fmaf(ry, w1.w, fmaf(rz, w2v.w, fmaf(rw, w3.w, h2.w))));
    }
    if (slot == 0)
        g_h2[(size_t)node * 4 + q] =
            make_float4(h2.x * dv, h2.y * dv, h2.z * dv, h2.w * dv);
}

// ---------------- agg2: sum_in(h2s) + self, *dinv, +b2, log_softmax ----------------
__global__ void k_agg2(const float* __restrict__ b2, float* __restrict__ out) {
    const int t = threadIdx.x;
    const int node = (int)((blockIdx.x * blockDim.x + t) >> 5);
    if (node >= N) return;
    const int lane = t & 31, slot = lane >> 2, q = lane & 3;
    const float4 b2q = __ldg(&((const float4*)b2)[q]);

    const int start = g_rowptr[node], end = g_rowptr[node + 1];
    float4 acc = make_float4(0.f, 0.f, 0.f, 0.f);
    for (int base = start; base < end; base += 32) {
        int e = base + lane;
        int s = (e < end) ? __ldg(&g_csrc[e]) : 0;
#pragma unroll
        for (int j = 0; j < 32; j += 8) {
            int jj = j + slot;
            int sj = __shfl_sync(0xffffffffu, s, jj);
            if (base + jj < end) {
                float4 hv = g_h2[(size_t)sj * 4 + q];
                acc.x += hv.x; acc.y += hv.y; acc.z += hv.z; acc.w += hv.w;
            }
        }
    }
#pragma unroll
    for (int o = 4; o < 32; o <<= 1) {
        acc.x += __shfl_xor_sync(0xffffffffu, acc.x, o);
        acc.y += __shfl_xor_sync(0xffffffffu, acc.y, o);
        acc.z += __shfl_xor_sync(0xffffffffu, acc.z, o);
        acc.w += __shfl_xor_sync(0xffffffffu, acc.w, o);
    }
    float dv = g_dinv[node];
    float4 sv = g_h2[(size_t)node * 4 + q];
    float4 val;
    val.x = (acc.x + sv.x) * dv + b2q.x;
    val.y = (acc.y + sv.y) * dv + b2q.y;
    val.z = (acc.z + sv.z) * dv + b2q.z;
    val.w = (acc.w + sv.w) * dv + b2q.w;

    float m = fmaxf(fmaxf(val.x, val.y), fmaxf(val.z, val.w));
    m = fmaxf(m, __shfl_xor_sync(0xffffffffu, m, 1));
    m = fmaxf(m, __shfl_xor_sync(0xffffffffu, m, 2));
    float ssum = __expf(val.x - m) + __expf(val.y - m) +
                 __expf(val.z - m) + __expf(val.w - m);
    ssum += __shfl_xor_sync(0xffffffffu, ssum, 1);
    ssum += __shfl_xor_sync(0xffffffffu, ssum, 2);
    float lse = m + __logf(ssum);
    if (slot == 0)
        ((float4*)out)[(size_t)node * 4 + q] =
            make_float4(val.x - lse, val.y - lse, val.z - lse, val.w - lse);
}

// ---------------- launch ----------------
extern "C" void kernel_launch(void* const* d_in, const int* in_sizes, int n_in,
                              void* d_out, int out_size) {
    const float* x  = (const float*)d_in[0];
    const float* W1 = (const float*)d_in[1];
    const float* b1 = (const float*)d_in[2];
    const float* W2 = (const float*)d_in[3];
    const float* b2 = (const float*)d_in[4];
    const int*   ei = (const int*)d_in[5];
    float* out = (float*)d_out;

    cudaFuncSetAttribute((const void*)k1,
                         cudaFuncAttributeMaxDynamicSharedMemorySize, SMEM_BYTES);

    k1             <<<GRID1, 256, SMEM_BYTES>>>(x, W1, ei);
    k_scan         <<<SCAN_BLOCKS, 256>>>();
    k_scatter_scale<<<1000, 256>>>(ei);
    k_agg1         <<<(N * 32 + 255) / 256, 256>>>(b1, W2);
    k_agg2         <<<(N * 32 + 255) / 256, 256>>>(b2, out);
}